// round 1
// baseline (speedup 1.0000x reference)
#include <cuda_runtime.h>

// ---------------------------------------------------------------------------
// Net_67765993996461: 3-layer spiking CNN (conv+LIF x3, FC, time-mean)
//   x  [32,1,128,40] fp32
//   w1 [64,1,4,3]  pad(2,1) dil(1,1) -> h [32,64,129,40]
//   w2 [64,64,4,3] pad(6,3) dil(4,3) -> shape preserved
//   w3 [64,64,4,3] pad(24,9) dil(16,9) -> shape preserved
//   LIF: v = v + (x - v)/tau (tau=10/7); s = (v>=1); v = s?0:v  (hard reset)
//   head: flatten (c,m) -> 2560, y = mean_t(h @ wf^T + bf)  -> [32,12]
// ---------------------------------------------------------------------------

#define TAUF ((float)(10.0 / 7.0))

constexpr int BB   = 32;
constexpr int CC   = 64;
constexpr int TT_  = 129;   // output time length
constexpr int TIN  = 128;   // input time length
constexpr int MM   = 40;
constexpr int N_SP = TT_ * MM;        // 5160 spatial positions per (b, c)
constexpr int LANES = BB * CC * MM;   // 81920
constexpr int VOL   = BB * CC * N_SP; // 10,567,680

// Scratch (device globals: allocation-free per harness rules)
__device__ float g_s1[VOL];
__device__ float g_u [VOL];
__device__ float g_s2[VOL];
__device__ float g_s3[VOL];
__device__ float g_w2t[CC * CC * 12];  // [ci][k][co]
__device__ float g_w3t[CC * CC * 12];
__device__ float g_ssum[BB * CC * MM];

// ---------------------------------------------------------------------------
// conv1 (C_in=1, 4x3 taps) fused with LIF over t. One thread per (b,c,m) lane.
// ---------------------------------------------------------------------------
__global__ void conv1_lif_kernel(const float* __restrict__ x,
                                 const float* __restrict__ w1) {
    int lane = blockIdx.x * blockDim.x + threadIdx.x;
    if (lane >= LANES) return;
    int m = lane % MM;
    int c = (lane / MM) % CC;
    int b = lane / (MM * CC);

    float w[12];
#pragma unroll
    for (int k = 0; k < 12; k++) w[k] = w1[c * 12 + k];

    const float* xb = x + b * TIN * MM;
    float* sp = g_s1 + (b * CC + c) * N_SP + m;

    float v = 0.f;
    for (int t = 0; t < TT_; t++) {
        float u = 0.f;
#pragma unroll
        for (int kt = 0; kt < 4; kt++) {
            int tt = t + kt - 2;
            if (tt < 0 || tt >= TIN) continue;
#pragma unroll
            for (int km = 0; km < 3; km++) {
                int mm = m + km - 1;
                if (mm < 0 || mm >= MM) continue;
                u += xb[tt * MM + mm] * w[kt * 3 + km];
            }
        }
        v = v + (u - v) / TAUF;            // IEEE div: match reference rounding
        float s = (v >= 1.0f) ? 1.0f : 0.0f;
        sp[t * MM] = s;
        v = (v >= 1.0f) ? 0.0f : v;        // hard reset
    }
}

// ---------------------------------------------------------------------------
// Weight transpose: w[co][ci][kt][km] -> wt[ci][k][co]  (coalesced A loads)
// ---------------------------------------------------------------------------
__global__ void wtrans_kernel(const float* __restrict__ w, int which) {
    float* wt = which ? g_w3t : g_w2t;
    int i = blockIdx.x * blockDim.x + threadIdx.x;
    if (i >= CC * CC * 12) return;
    int co = i / (CC * 12);
    int rest = i % (CC * 12);  // ci*12 + k
    wt[rest * CC + co] = w[i];
}

// ---------------------------------------------------------------------------
// Dilated conv as implicit GEMM: C[64co x 128n] per block, 8x8 per thread.
// LAYER==2: g_s1 x g_w2t -> g_u ; LAYER==3: g_s2 x g_w3t -> g_u
// ---------------------------------------------------------------------------
template <int LAYER, int DT, int PT, int DM, int PM>
__global__ void conv_gemm_kernel() {
    const float* __restrict__ in = (LAYER == 2) ? g_s1 : g_s2;
    const float* __restrict__ wt = (LAYER == 2) ? g_w2t : g_w3t;
    float* __restrict__ out = g_u;

    __shared__ float As[12][64];    // [k][co]
    __shared__ float Bs[12][128];   // [k][n]

    int b  = blockIdx.y;
    int n0 = blockIdx.x * 128;
    int tid = threadIdx.x;          // 0..127
    int tx = tid & 15;              // n sub-group
    int ty = tid >> 4;              // co sub-group 0..7

    float acc[8][8];
#pragma unroll
    for (int i = 0; i < 8; i++)
#pragma unroll
        for (int j = 0; j < 8; j++) acc[i][j] = 0.f;

    int ng = n0 + tid;
    int tt0 = ng / MM;
    int mm0 = ng % MM;
    bool nvalid = (ng < N_SP);
    const float* inb = in + b * (CC * N_SP);

    for (int ci = 0; ci < CC; ci++) {
        // A: 768 elems (12 k x 64 co), contiguous in wt -> coalesced
        const float* wci = wt + ci * (12 * CC);
#pragma unroll
        for (int r = 0; r < 6; r++) {
            int e = tid + r * 128;
            (&As[0][0])[e] = wci[e];
        }
        // B: im2col gather, 12 per thread (all k at n=ng)
        const float* inc = inb + ci * N_SP;
#pragma unroll
        for (int k = 0; k < 12; k++) {
            int kt = k / 3, km = k % 3;
            int tt = tt0 + DT * kt - PT;
            int mm = mm0 + DM * km - PM;
            float vz = 0.f;
            if (nvalid && tt >= 0 && tt < TT_ && mm >= 0 && mm < MM)
                vz = inc[tt * MM + mm];
            Bs[k][tid] = vz;
        }
        __syncthreads();
#pragma unroll
        for (int k = 0; k < 12; k++) {
            float a[8], bv[8];
#pragma unroll
            for (int i = 0; i < 8; i++) a[i] = As[k][ty * 8 + i];
#pragma unroll
            for (int j = 0; j < 4; j++) {
                bv[j]     = Bs[k][tx * 4 + j];
                bv[4 + j] = Bs[k][64 + tx * 4 + j];
            }
#pragma unroll
            for (int i = 0; i < 8; i++)
#pragma unroll
                for (int j = 0; j < 8; j++) acc[i][j] += a[i] * bv[j];
        }
        __syncthreads();
    }

    // store: out[b][co][n], n = t*40+m flattened
#pragma unroll
    for (int i = 0; i < 8; i++) {
        int co = ty * 8 + i;
        float* op = out + (b * CC + co) * N_SP;
#pragma unroll
        for (int seg = 0; seg < 2; seg++) {
            int n = n0 + seg * 64 + tx * 4;
            if (n + 3 < N_SP) {
                float4 vv = make_float4(acc[i][seg * 4 + 0], acc[i][seg * 4 + 1],
                                        acc[i][seg * 4 + 2], acc[i][seg * 4 + 3]);
                *(float4*)(op + n) = vv;
            } else {
#pragma unroll
                for (int j = 0; j < 4; j++)
                    if (n + j < N_SP) op[n + j] = acc[i][seg * 4 + j];
            }
        }
    }
}

// ---------------------------------------------------------------------------
// LIF over t for a full [B,C,T,M] buffer. which==0 -> g_s2, which==1 -> g_s3
// ---------------------------------------------------------------------------
__global__ void lif_kernel(int which) {
    float* s = which ? g_s3 : g_s2;
    int lane = blockIdx.x * blockDim.x + threadIdx.x;
    if (lane >= LANES) return;
    int m = lane % MM;
    int bc = lane / MM;
    const float* up = g_u + bc * N_SP + m;
    float* sp = s + bc * N_SP + m;
    float v = 0.f;
    for (int t = 0; t < TT_; t++) {
        float xx = up[t * MM];
        v = v + (xx - v) / TAUF;
        float sv = (v >= 1.0f) ? 1.0f : 0.0f;
        sp[t * MM] = sv;
        v = (v >= 1.0f) ? 0.0f : v;
    }
}

// ---------------------------------------------------------------------------
// Time-sum of spikes: ssum[b][c*40+m] = sum_t s3[b][c][t][m]
// ---------------------------------------------------------------------------
__global__ void tsum_kernel() {
    int lane = blockIdx.x * blockDim.x + threadIdx.x;
    if (lane >= LANES) return;
    int m = lane % MM;
    int bc = lane / MM;
    const float* sp = g_s3 + bc * N_SP + m;
    float acc = 0.f;
    for (int t = 0; t < TT_; t++) acc += sp[t * MM];
    g_ssum[bc * MM + m] = acc;   // = b*2560 + c*40 + m
}

// ---------------------------------------------------------------------------
// y[b][j] = dot(ssum[b,:], wf[j,:]) / 129 + bf[j]
// ---------------------------------------------------------------------------
__global__ void fc_kernel(const float* __restrict__ wf,
                          const float* __restrict__ bf,
                          float* __restrict__ y) {
    int b = blockIdx.x, j = blockIdx.y;
    int tid = threadIdx.x;  // 128
    const float* sb = g_ssum + b * (CC * MM);
    const float* wj = wf + j * (CC * MM);
    float acc = 0.f;
    for (int i = tid; i < CC * MM; i += 128) acc += sb[i] * wj[i];
    __shared__ float red[128];
    red[tid] = acc;
    __syncthreads();
    for (int s = 64; s > 0; s >>= 1) {
        if (tid < s) red[tid] += red[tid + s];
        __syncthreads();
    }
    if (tid == 0) y[b * 12 + j] = red[0] * (1.0f / 129.0f) + bf[j];
}

// ---------------------------------------------------------------------------
extern "C" void kernel_launch(void* const* d_in, const int* in_sizes, int n_in,
                              void* d_out, int out_size) {
    const float* x  = (const float*)d_in[0];
    const float* w1 = (const float*)d_in[1];
    const float* w2 = (const float*)d_in[2];
    const float* w3 = (const float*)d_in[3];
    const float* wf = (const float*)d_in[4];
    const float* bf = (const float*)d_in[5];
    float* y = (float*)d_out;

    // weight transposes (cheap, deterministic every call)
    wtrans_kernel<<<(CC * CC * 12 + 255) / 256, 256>>>(w2, 0);
    wtrans_kernel<<<(CC * CC * 12 + 255) / 256, 256>>>(w3, 1);

    // layer 1: conv1 + LIF fused
    conv1_lif_kernel<<<(LANES + 255) / 256, 256>>>(x, w1);

    // layer 2: conv (dil 4,3 / pad 6,3) then LIF
    {
        dim3 grid((N_SP + 127) / 128, BB);
        conv_gemm_kernel<2, 4, 6, 3, 3><<<grid, 128>>>();
    }
    lif_kernel<<<(LANES + 255) / 256, 256>>>(0);

    // layer 3: conv (dil 16,9 / pad 24,9) then LIF
    {
        dim3 grid((N_SP + 127) / 128, BB);
        conv_gemm_kernel<3, 16, 24, 9, 9><<<grid, 128>>>();
    }
    lif_kernel<<<(LANES + 255) / 256, 256>>>(1);

    // head
    tsum_kernel<<<(LANES + 255) / 256, 256>>>();
    {
        dim3 grid(BB, 12);
        fc_kernel<<<grid, 128>>>(wf, bf, y);
    }
}

// round 2
// speedup vs baseline: 1.6661x; 1.6661x over previous
#include <cuda_runtime.h>
#include <cuda_bf16.h>

// ---------------------------------------------------------------------------
// Net_67765993996461: 3-layer spiking CNN (conv+LIF x3, FC, time-mean)
// R2: conv2/conv3 via mma.sync.m16n8k16.bf16 with exact 3-way bf16 weight split
// ---------------------------------------------------------------------------

#define TAUF ((float)(10.0 / 7.0))

constexpr int BB   = 32;
constexpr int CC   = 64;
constexpr int TT_  = 129;   // output time length
constexpr int TIN  = 128;   // input time length
constexpr int MM   = 40;
constexpr int N_SP = TT_ * MM;        // 5160
constexpr int LANES = BB * CC * MM;   // 81920
constexpr int VOL   = BB * CC * N_SP; // 10,567,680
constexpr int KK    = CC * 12;        // 768 = GEMM K per split

// Scratch (device globals)
__device__ __nv_bfloat16 g_s1[VOL];
__device__ float         g_u [VOL];
__device__ __nv_bfloat16 g_s2[VOL];
__device__ __nv_bfloat16 g_s3[VOL];
__device__ __nv_bfloat16 g_w2s[3 * CC * KK];  // [split][co][K], K = ci*12 + kt*3 + km
__device__ __nv_bfloat16 g_w3s[3 * CC * KK];
__device__ float         g_ssum[BB * CC * MM];

// ---------------------------------------------------------------------------
// conv1 (C_in=1) fused with LIF. One thread per (b,c,m) lane. bf16 spikes out.
// ---------------------------------------------------------------------------
__global__ void conv1_lif_kernel(const float* __restrict__ x,
                                 const float* __restrict__ w1) {
    int lane = blockIdx.x * blockDim.x + threadIdx.x;
    if (lane >= LANES) return;
    int m = lane % MM;
    int c = (lane / MM) % CC;
    int b = lane / (MM * CC);

    float w[12];
#pragma unroll
    for (int k = 0; k < 12; k++) w[k] = w1[c * 12 + k];

    const float* xb = x + b * TIN * MM;
    __nv_bfloat16* sp = g_s1 + (size_t)(b * CC + c) * N_SP + m;

    float v = 0.f;
    for (int t = 0; t < TT_; t++) {
        float u = 0.f;
#pragma unroll
        for (int kt = 0; kt < 4; kt++) {
            int tt = t + kt - 2;
            if (tt < 0 || tt >= TIN) continue;
#pragma unroll
            for (int km = 0; km < 3; km++) {
                int mm = m + km - 1;
                if (mm < 0 || mm >= MM) continue;
                u += xb[tt * MM + mm] * w[kt * 3 + km];
            }
        }
        v = v + (u - v) / TAUF;
        float s = (v >= 1.0f) ? 1.0f : 0.0f;
        sp[t * MM] = __float2bfloat16(s);
        v = (v >= 1.0f) ? 0.0f : v;
    }
}

// ---------------------------------------------------------------------------
// Exact 3-way bf16 split (RZ truncation: clean 8+8+8 bit partition of fp32).
// Layout: ws[split][co*768 + K] where K matches w's native [co][ci][kt][km].
// ---------------------------------------------------------------------------
__global__ void wsplit_kernel(const float* __restrict__ w, int which) {
    __nv_bfloat16* ws = which ? g_w3s : g_w2s;
    int i = blockIdx.x * blockDim.x + threadIdx.x;
    if (i >= CC * KK) return;
    float v = w[i];
    __nv_bfloat16 h0 = __float2bfloat16_rz(v);
    float r1 = v - __bfloat162float(h0);
    __nv_bfloat16 h1 = __float2bfloat16_rz(r1);
    float r2 = r1 - __bfloat162float(h1);
    __nv_bfloat16 h2 = __float2bfloat16_rz(r2);
    ws[i]             = h0;
    ws[CC * KK + i]   = h1;
    ws[2 * CC * KK + i] = h2;
}

// ---------------------------------------------------------------------------
// mma helper
// ---------------------------------------------------------------------------
__device__ __forceinline__ void mma16816(float* d, const unsigned* a, const unsigned* b) {
    asm volatile(
        "mma.sync.aligned.m16n8k16.row.col.f32.bf16.bf16.f32 "
        "{%0,%1,%2,%3}, {%4,%5,%6,%7}, {%8,%9}, {%0,%1,%2,%3};\n"
        : "+f"(d[0]), "+f"(d[1]), "+f"(d[2]), "+f"(d[3])
        : "r"(a[0]), "r"(a[1]), "r"(a[2]), "r"(a[3]), "r"(b[0]), "r"(b[1]));
}

// ---------------------------------------------------------------------------
// Dilated conv as tensor-core GEMM: C[64co x 128n] per block, 8 warps.
// Warp tile 32co x 32n. K = 768 per split, 3 splits, chunked at KC=48.
// ---------------------------------------------------------------------------
template <int LAYER, int DT, int PT, int DM, int PM>
__global__ void conv_mma_kernel() {
    constexpr int KC = 48;
    constexpr int NCH = KK / KC;   // 16
    constexpr int APAD = 56;       // As k-stride (mult of 8 for uint4 STS align)
    constexpr int BPAD = 58;       // Bs k-stride (odd bank stride: conflict-free)

    __shared__ __nv_bfloat16 As[3][64][APAD];  // [split][co][k]
    __shared__ __nv_bfloat16 Bs[128][BPAD];    // [n][k]

    const __nv_bfloat16* __restrict__ in = (LAYER == 2) ? g_s1 : g_s2;
    const __nv_bfloat16* __restrict__ ws = (LAYER == 2) ? g_w2s : g_w3s;

    int b  = blockIdx.y;
    int n0 = blockIdx.x * 128;
    int tid  = threadIdx.x;        // 0..255
    int warp = tid >> 5;
    int lane = tid & 31;
    int wco = (warp >> 2) * 32;    // 0 or 32
    int wn  = (warp & 3) * 32;     // 0/32/64/96

    float acc[2][4][4];
#pragma unroll
    for (int i = 0; i < 2; i++)
#pragma unroll
        for (int j = 0; j < 4; j++)
#pragma unroll
            for (int q = 0; q < 4; q++) acc[i][j][q] = 0.f;

    // B gather mapping: column n_loc, rows kk = (tid>>7) + 2*j
    int n_loc = tid & 127;
    int half  = tid >> 7;
    int ng  = n0 + n_loc;
    int tt0 = ng / MM;
    int mm0 = ng % MM;
    bool nv = (ng < N_SP);
    const __nv_bfloat16* inb = in + (size_t)b * CC * N_SP;

    int lrow = lane >> 2;          // 0..7
    int lk   = (lane & 3) * 2;     // 0,2,4,6

    for (int ch = 0; ch < NCH; ch++) {
        int K0 = ch * KC;

        // fill As: 192 rows x 48 bf16 (96B = 6 uint4 each)
        for (int i = tid; i < 192 * 6; i += 256) {
            int row = i / 6, q = i % 6;       // row = split*64 + co
            int split = row >> 6, co = row & 63;
            const uint4* src = (const uint4*)(ws + ((size_t)split * CC + co) * KK + K0);
            *(uint4*)(&As[split][co][q * 8]) = src[q];
        }
        // fill Bs: im2col gather (bf16, mostly coalesced across n)
#pragma unroll
        for (int j = 0; j < KC / 2; j++) {
            int kk = half + 2 * j;
            int K = K0 + kk;
            int ci = K / 12;
            int k  = K - ci * 12;
            int kt = k / 3;
            int km = k - kt * 3;
            int tt = tt0 + DT * kt - PT;
            int mm = mm0 + DM * km - PM;
            __nv_bfloat16 v = __float2bfloat16(0.f);
            if (nv && tt >= 0 && tt < TT_ && mm >= 0 && mm < MM)
                v = inb[(size_t)ci * N_SP + tt * MM + mm];
            Bs[n_loc][kk] = v;
        }
        __syncthreads();

#pragma unroll
        for (int ks = 0; ks < KC / 16; ks++) {
            int k0 = ks * 16;
            unsigned bfrag[4][2];
#pragma unroll
            for (int nf = 0; nf < 4; nf++) {
                const __nv_bfloat16* bp = &Bs[wn + nf * 8 + lrow][k0 + lk];
                bfrag[nf][0] = *(const unsigned*)(bp);
                bfrag[nf][1] = *(const unsigned*)(bp + 8);
            }
#pragma unroll
            for (int s = 0; s < 3; s++) {
#pragma unroll
                for (int mf = 0; mf < 2; mf++) {
                    int aco = wco + mf * 16 + lrow;
                    unsigned af[4];
                    af[0] = *(const unsigned*)&As[s][aco][k0 + lk];
                    af[1] = *(const unsigned*)&As[s][aco + 8][k0 + lk];
                    af[2] = *(const unsigned*)&As[s][aco][k0 + lk + 8];
                    af[3] = *(const unsigned*)&As[s][aco + 8][k0 + lk + 8];
#pragma unroll
                    for (int nf = 0; nf < 4; nf++)
                        mma16816(acc[mf][nf], af, bfrag[nf]);
                }
            }
        }
        __syncthreads();
    }

    // epilogue: C fragment c0/c1 = (row lrow, cols lk,lk+1), c2/c3 = row+8
    float* outb = g_u + (size_t)b * CC * N_SP;
#pragma unroll
    for (int mf = 0; mf < 2; mf++) {
#pragma unroll
        for (int nf = 0; nf < 4; nf++) {
            int co = wco + mf * 16 + lrow;
            int n  = n0 + wn + nf * 8 + lk;
            float* p  = outb + (size_t)co * N_SP + n;
            float* p2 = outb + (size_t)(co + 8) * N_SP + n;
            if (n + 1 < N_SP) {
                *(float2*)p  = make_float2(acc[mf][nf][0], acc[mf][nf][1]);
                *(float2*)p2 = make_float2(acc[mf][nf][2], acc[mf][nf][3]);
            } else if (n < N_SP) {
                p[0]  = acc[mf][nf][0];
                p2[0] = acc[mf][nf][2];
            }
        }
    }
}

// ---------------------------------------------------------------------------
// LIF over t. which==0 -> g_s2, which==1 -> g_s3 (bf16 spikes)
// ---------------------------------------------------------------------------
__global__ void lif_kernel(int which) {
    __nv_bfloat16* s = which ? g_s3 : g_s2;
    int lane = blockIdx.x * blockDim.x + threadIdx.x;
    if (lane >= LANES) return;
    int m = lane % MM;
    int bc = lane / MM;
    const float* up = g_u + (size_t)bc * N_SP + m;
    __nv_bfloat16* sp = s + (size_t)bc * N_SP + m;
    float v = 0.f;
    for (int t = 0; t < TT_; t++) {
        float xx = up[t * MM];
        v = v + (xx - v) / TAUF;
        float sv = (v >= 1.0f) ? 1.0f : 0.0f;
        sp[t * MM] = __float2bfloat16(sv);
        v = (v >= 1.0f) ? 0.0f : v;
    }
}

// ---------------------------------------------------------------------------
// Time-sum of spikes: ssum[b][c*40+m] = sum_t s3[b][c][t][m]
// ---------------------------------------------------------------------------
__global__ void tsum_kernel() {
    int lane = blockIdx.x * blockDim.x + threadIdx.x;
    if (lane >= LANES) return;
    int m = lane % MM;
    int bc = lane / MM;
    const __nv_bfloat16* sp = g_s3 + (size_t)bc * N_SP + m;
    float acc = 0.f;
    for (int t = 0; t < TT_; t++) acc += __bfloat162float(sp[t * MM]);
    g_ssum[bc * MM + m] = acc;
}

// ---------------------------------------------------------------------------
// y[b][j] = dot(ssum[b,:], wf[j,:]) / 129 + bf[j]
// ---------------------------------------------------------------------------
__global__ void fc_kernel(const float* __restrict__ wf,
                          const float* __restrict__ bf,
                          float* __restrict__ y) {
    int b = blockIdx.x, j = blockIdx.y;
    int tid = threadIdx.x;  // 128
    const float* sb = g_ssum + b * (CC * MM);
    const float* wj = wf + j * (CC * MM);
    float acc = 0.f;
    for (int i = tid; i < CC * MM; i += 128) acc += sb[i] * wj[i];
    __shared__ float red[128];
    red[tid] = acc;
    __syncthreads();
    for (int s = 64; s > 0; s >>= 1) {
        if (tid < s) red[tid] += red[tid + s];
        __syncthreads();
    }
    if (tid == 0) y[b * 12 + j] = red[0] * (1.0f / 129.0f) + bf[j];
}

// ---------------------------------------------------------------------------
extern "C" void kernel_launch(void* const* d_in, const int* in_sizes, int n_in,
                              void* d_out, int out_size) {
    const float* x  = (const float*)d_in[0];
    const float* w1 = (const float*)d_in[1];
    const float* w2 = (const float*)d_in[2];
    const float* w3 = (const float*)d_in[3];
    const float* wf = (const float*)d_in[4];
    const float* bf = (const float*)d_in[5];
    float* y = (float*)d_out;

    wsplit_kernel<<<(CC * KK + 255) / 256, 256>>>(w2, 0);
    wsplit_kernel<<<(CC * KK + 255) / 256, 256>>>(w3, 1);

    conv1_lif_kernel<<<(LANES + 255) / 256, 256>>>(x, w1);

    {
        dim3 grid((N_SP + 127) / 128, BB);
        conv_mma_kernel<2, 4, 6, 3, 3><<<grid, 256>>>();
    }
    lif_kernel<<<(LANES + 255) / 256, 256>>>(0);

    {
        dim3 grid((N_SP + 127) / 128, BB);
        conv_mma_kernel<3, 16, 24, 9, 9><<<grid, 256>>>();
    }
    lif_kernel<<<(LANES + 255) / 256, 256>>>(1);

    tsum_kernel<<<(LANES + 255) / 256, 256>>>();
    {
        dim3 grid(BB, 12);
        fc_kernel<<<grid, 128>>>(wf, bf, y);
    }
}

// round 3
// speedup vs baseline: 2.4553x; 1.4737x over previous
#include <cuda_runtime.h>
#include <cuda_bf16.h>

// ---------------------------------------------------------------------------
// Net_67765993996461  R3: tap-decomposed tensor-core convs + ldmatrix +
// double-buffered smem pipeline. Exact 3-way bf16 weight split (unchanged).
// ---------------------------------------------------------------------------

#define TAUF ((float)(10.0 / 7.0))

constexpr int BB   = 32;
constexpr int CC   = 64;
constexpr int TT_  = 129;
constexpr int TIN  = 128;
constexpr int MM   = 40;
constexpr int N_SP = TT_ * MM;        // 5160
constexpr int LANES = BB * CC * MM;   // 81920
constexpr int VOL   = BB * CC * N_SP; // 10,567,680

constexpr int AP = 72;    // As row stride (elems): 9 quads -> LDSM conflict-free
constexpr int BP = 136;   // Bs row stride (elems): 17 quads -> LDSM conflict-free
constexpr int SMEM_BYTES = (2 * 192 * AP + 2 * 64 * BP) * 2;  // 90112 B

// Scratch
__device__ __nv_bfloat16 g_s1[VOL];
__device__ float         g_u [VOL];
__device__ __nv_bfloat16 g_s2[VOL];
__device__ __nv_bfloat16 g_s3[VOL];
__device__ __nv_bfloat16 g_w2s[12 * 3 * CC * CC];  // [tap][split][co][ci]
__device__ __nv_bfloat16 g_w3s[12 * 3 * CC * CC];
__device__ float         g_ssum[BB * CC * MM];

// ---------------------------------------------------------------------------
__global__ void conv1_lif_kernel(const float* __restrict__ x,
                                 const float* __restrict__ w1) {
    int lane = blockIdx.x * blockDim.x + threadIdx.x;
    if (lane >= LANES) return;
    int m = lane % MM;
    int c = (lane / MM) % CC;
    int b = lane / (MM * CC);

    float w[12];
#pragma unroll
    for (int k = 0; k < 12; k++) w[k] = w1[c * 12 + k];

    const float* xb = x + b * TIN * MM;
    __nv_bfloat16* sp = g_s1 + (size_t)(b * CC + c) * N_SP + m;

    float v = 0.f;
    for (int t = 0; t < TT_; t++) {
        float u = 0.f;
#pragma unroll
        for (int kt = 0; kt < 4; kt++) {
            int tt = t + kt - 2;
            if (tt < 0 || tt >= TIN) continue;
#pragma unroll
            for (int km = 0; km < 3; km++) {
                int mm = m + km - 1;
                if (mm < 0 || mm >= MM) continue;
                u += xb[tt * MM + mm] * w[kt * 3 + km];
            }
        }
        v = v + (u - v) / TAUF;
        float s = (v >= 1.0f) ? 1.0f : 0.0f;
        sp[t * MM] = __float2bfloat16(s);
        v = (v >= 1.0f) ? 0.0f : v;
    }
}

// ---------------------------------------------------------------------------
// Exact 3-way bf16 split, layout [tap][split][co][ci]
// ---------------------------------------------------------------------------
__global__ void wsplit_kernel(const float* __restrict__ w, int which) {
    __nv_bfloat16* ws = which ? g_w3s : g_w2s;
    int i = blockIdx.x * blockDim.x + threadIdx.x;   // i = co*768 + ci*12 + tap
    if (i >= CC * CC * 12) return;
    int co  = i / 768;
    int r   = i - co * 768;
    int ci  = r / 12;
    int tap = r - ci * 12;
    float v = w[i];
    __nv_bfloat16 h0 = __float2bfloat16_rz(v);
    float r1 = v - __bfloat162float(h0);
    __nv_bfloat16 h1 = __float2bfloat16_rz(r1);
    float r2 = r1 - __bfloat162float(h1);
    __nv_bfloat16 h2 = __float2bfloat16_rz(r2);
    ws[((tap * 3 + 0) * CC + co) * CC + ci] = h0;
    ws[((tap * 3 + 1) * CC + co) * CC + ci] = h1;
    ws[((tap * 3 + 2) * CC + co) * CC + ci] = h2;
}

// ---------------------------------------------------------------------------
__device__ __forceinline__ void mma16816(float* d, const unsigned* a, const unsigned* b) {
    asm volatile(
        "mma.sync.aligned.m16n8k16.row.col.f32.bf16.bf16.f32 "
        "{%0,%1,%2,%3}, {%4,%5,%6,%7}, {%8,%9}, {%0,%1,%2,%3};\n"
        : "+f"(d[0]), "+f"(d[1]), "+f"(d[2]), "+f"(d[3])
        : "r"(a[0]), "r"(a[1]), "r"(a[2]), "r"(a[3]), "r"(b[0]), "r"(b[1]));
}
__device__ __forceinline__ void ldsm_x4(unsigned addr, unsigned& r0, unsigned& r1,
                                        unsigned& r2, unsigned& r3) {
    asm volatile("ldmatrix.sync.aligned.m8n8.x4.shared.b16 {%0,%1,%2,%3}, [%4];\n"
                 : "=r"(r0), "=r"(r1), "=r"(r2), "=r"(r3) : "r"(addr));
}
__device__ __forceinline__ void ldsm_x4_t(unsigned addr, unsigned& r0, unsigned& r1,
                                          unsigned& r2, unsigned& r3) {
    asm volatile("ldmatrix.sync.aligned.m8n8.x4.trans.shared.b16 {%0,%1,%2,%3}, [%4];\n"
                 : "=r"(r0), "=r"(r1), "=r"(r2), "=r"(r3) : "r"(addr));
}
__device__ __forceinline__ unsigned smem_u32(const void* p) {
    return (unsigned)__cvta_generic_to_shared(p);
}

// ---------------------------------------------------------------------------
// Tap-decomposed conv GEMM. Block: 64co x 128n, 8 warps (32co x 32n each).
// Per tap: As[split][co][ci] (24KB), Bs[ci][n] (shifted spike plane slice).
// ---------------------------------------------------------------------------
template <int LAYER, int DT, int PT, int DM, int PM>
__global__ __launch_bounds__(256, 2) void conv_mma_kernel() {
    extern __shared__ __nv_bfloat16 sm[];
    __nv_bfloat16* As = sm;                  // [2][3*64][AP]
    __nv_bfloat16* Bs = sm + 2 * 192 * AP;   // [2][64][BP]

    const __nv_bfloat16* __restrict__ in = (LAYER == 2) ? g_s1 : g_s2;
    const __nv_bfloat16* __restrict__ ws = (LAYER == 2) ? g_w2s : g_w3s;

    int b  = blockIdx.y;
    int n0 = blockIdx.x * 128;
    int tid  = threadIdx.x;
    int warp = tid >> 5, lane = tid & 31;
    int wco = (warp >> 2) * 32;
    int wn  = (warp & 3) * 32;

    const __nv_bfloat16* inb = in + (size_t)b * CC * N_SP;

    // gather mapping: thread owns one n column, half the ci range
    int nl   = tid & 127;
    int half = tid >> 7;
    int ng  = n0 + nl;
    int tt0 = ng / MM;
    int mm0 = ng - tt0 * MM;

    float acc[2][4][4];
#pragma unroll
    for (int i = 0; i < 2; i++)
#pragma unroll
        for (int j = 0; j < 4; j++)
#pragma unroll
            for (int q = 0; q < 4; q++) acc[i][j][q] = 0.f;

    const __nv_bfloat16 BZERO = __float2bfloat16(0.f);

    auto fill = [&](int tap, int sel) {
        // A: [tap][3][64co][64ci] -> As[sel], contiguous uint4 source
        const uint4* wsrc = (const uint4*)(ws + (size_t)tap * 3 * CC * CC);
        __nv_bfloat16* Ad = As + sel * 192 * AP;
#pragma unroll
        for (int r = 0; r < 6; r++) {
            int i = tid + r * 256;
            int row = i >> 3, q = i & 7;
            *(uint4*)(Ad + row * AP + q * 8) = wsrc[i];
        }
        // B: shifted plane gather, predicate fixed per (thread, tap)
        int kt = tap / 3, km = tap - kt * 3;
        int toff = DT * kt - PT, moff = DM * km - PM;
        int tt = tt0 + toff, mm = mm0 + moff;
        bool p = (tt >= 0) & (tt < TT_) & (mm >= 0) & (mm < MM);
        const __nv_bfloat16* src = inb + (size_t)(half * 32) * N_SP + (tt * MM + mm);
        __nv_bfloat16* Bd = Bs + sel * 64 * BP + (half * 32) * BP + nl;
        if (p) {
#pragma unroll
            for (int c = 0; c < 32; c++) Bd[c * BP] = src[(size_t)c * N_SP];
        } else {
#pragma unroll
            for (int c = 0; c < 32; c++) Bd[c * BP] = BZERO;
        }
    };

    auto domma = [&](int sel) {
        const __nv_bfloat16* Ab = As + sel * 192 * AP;
        const __nv_bfloat16* Bb = Bs + sel * 64 * BP;
#pragma unroll
        for (int ks = 0; ks < 4; ks++) {
            int k0 = ks * 16;
            unsigned bf[4][2];
#pragma unroll
            for (int g = 0; g < 2; g++) {
                unsigned addr = smem_u32(Bb + (k0 + (lane & 15)) * BP +
                                         wn + g * 16 + (lane >> 4) * 8);
                unsigned r0, r1, r2, r3;
                ldsm_x4_t(addr, r0, r1, r2, r3);
                bf[2 * g][0] = r0; bf[2 * g][1] = r1;
                bf[2 * g + 1][0] = r2; bf[2 * g + 1][1] = r3;
            }
#pragma unroll
            for (int s = 0; s < 3; s++) {
#pragma unroll
                for (int mf = 0; mf < 2; mf++) {
                    unsigned addr = smem_u32(Ab + (s * 64 + wco + mf * 16 + (lane & 15)) * AP +
                                             k0 + (lane >> 4) * 8);
                    unsigned a[4];
                    ldsm_x4(addr, a[0], a[1], a[2], a[3]);
#pragma unroll
                    for (int nf = 0; nf < 4; nf++)
                        mma16816(acc[mf][nf], a, bf[nf]);
                }
            }
        }
    };

    fill(0, 0);
    __syncthreads();
#pragma unroll
    for (int tap = 0; tap < 12; tap++) {
        domma(tap & 1);
        if (tap < 11) fill(tap + 1, (tap + 1) & 1);
        __syncthreads();
    }

    // epilogue
    int lrow = lane >> 2, lk = (lane & 3) * 2;
    float* outb = g_u + (size_t)b * CC * N_SP;
#pragma unroll
    for (int mf = 0; mf < 2; mf++) {
#pragma unroll
        for (int nf = 0; nf < 4; nf++) {
            int co = wco + mf * 16 + lrow;
            int n  = n0 + wn + nf * 8 + lk;
            float* p1 = outb + (size_t)co * N_SP + n;
            float* p2 = outb + (size_t)(co + 8) * N_SP + n;
            if (n + 1 < N_SP) {
                *(float2*)p1 = make_float2(acc[mf][nf][0], acc[mf][nf][1]);
                *(float2*)p2 = make_float2(acc[mf][nf][2], acc[mf][nf][3]);
            } else if (n < N_SP) {
                p1[0] = acc[mf][nf][0];
                p2[0] = acc[mf][nf][2];
            }
        }
    }
}

// ---------------------------------------------------------------------------
__global__ void lif_kernel(int which) {
    __nv_bfloat16* s = which ? g_s3 : g_s2;
    int lane = blockIdx.x * blockDim.x + threadIdx.x;
    if (lane >= LANES) return;
    int m = lane % MM;
    int bc = lane / MM;
    const float* up = g_u + (size_t)bc * N_SP + m;
    __nv_bfloat16* sp = s + (size_t)bc * N_SP + m;
    float v = 0.f;
    for (int t = 0; t < TT_; t++) {
        float xx = up[t * MM];
        v = v + (xx - v) / TAUF;
        float sv = (v >= 1.0f) ? 1.0f : 0.0f;
        sp[t * MM] = __float2bfloat16(sv);
        v = (v >= 1.0f) ? 0.0f : v;
    }
}

__global__ void tsum_kernel() {
    int lane = blockIdx.x * blockDim.x + threadIdx.x;
    if (lane >= LANES) return;
    int m = lane % MM;
    int bc = lane / MM;
    const __nv_bfloat16* sp = g_s3 + (size_t)bc * N_SP + m;
    float acc = 0.f;
    for (int t = 0; t < TT_; t++) acc += __bfloat162float(sp[t * MM]);
    g_ssum[bc * MM + m] = acc;
}

__global__ void fc_kernel(const float* __restrict__ wf,
                          const float* __restrict__ bf,
                          float* __restrict__ y) {
    int b = blockIdx.x, j = blockIdx.y;
    int tid = threadIdx.x;
    const float* sb = g_ssum + b * (CC * MM);
    const float* wj = wf + j * (CC * MM);
    float acc = 0.f;
    for (int i = tid; i < CC * MM; i += 128) acc += sb[i] * wj[i];
    __shared__ float red[128];
    red[tid] = acc;
    __syncthreads();
    for (int s = 64; s > 0; s >>= 1) {
        if (tid < s) red[tid] += red[tid + s];
        __syncthreads();
    }
    if (tid == 0) y[b * 12 + j] = red[0] * (1.0f / 129.0f) + bf[j];
}

// ---------------------------------------------------------------------------
extern "C" void kernel_launch(void* const* d_in, const int* in_sizes, int n_in,
                              void* d_out, int out_size) {
    const float* x  = (const float*)d_in[0];
    const float* w1 = (const float*)d_in[1];
    const float* w2 = (const float*)d_in[2];
    const float* w3 = (const float*)d_in[3];
    const float* wf = (const float*)d_in[4];
    const float* bf = (const float*)d_in[5];
    float* y = (float*)d_out;

    static int smem_set = 0;
    if (!smem_set) {
        cudaFuncSetAttribute(conv_mma_kernel<2, 4, 6, 3, 3>,
                             cudaFuncAttributeMaxDynamicSharedMemorySize, SMEM_BYTES);
        cudaFuncSetAttribute(conv_mma_kernel<3, 16, 24, 9, 9>,
                             cudaFuncAttributeMaxDynamicSharedMemorySize, SMEM_BYTES);
        smem_set = 1;
    }

    wsplit_kernel<<<(CC * CC * 12 + 255) / 256, 256>>>(w2, 0);
    wsplit_kernel<<<(CC * CC * 12 + 255) / 256, 256>>>(w3, 1);

    conv1_lif_kernel<<<(LANES + 255) / 256, 256>>>(x, w1);

    {
        dim3 grid((N_SP + 127) / 128, BB);
        conv_mma_kernel<2, 4, 6, 3, 3><<<grid, 256, SMEM_BYTES>>>();
    }
    lif_kernel<<<(LANES + 255) / 256, 256>>>(0);

    {
        dim3 grid((N_SP + 127) / 128, BB);
        conv_mma_kernel<3, 16, 24, 9, 9><<<grid, 256, SMEM_BYTES>>>();
    }
    lif_kernel<<<(LANES + 255) / 256, 256>>>(1);

    tsum_kernel<<<(LANES + 255) / 256, 256>>>();
    {
        dim3 grid(BB, 12);
        fc_kernel<<<grid, 128>>>(wf, bf, y);
    }
}